// round 16
// baseline (speedup 1.0000x reference)
#include <cuda_runtime.h>

#define NTOT 50000
#define AANCH 32
#define DDIM 64
#define NG 3125                      // NTOT/16
#define UB 8                         // u's per producer block
#define NPREPG 391                   // G2 producer blocks (391*8 >= 3125)
#define NPREP 392                    // producers incl. anchor block
#define MROWS 64                     // rows per block (main phase)
#define GRID 782                     // (NTOT + MROWS - 1) / MROWS

// plain C: g_C[a*64+k] = (1/32) * embeds[anchor[a]] . W1[k,:]
__device__ __align__(16) float g_C[AANCH * DDIM];
// pair-G: g_G2[u*64+k] = (E16[u]+E16[(u+1)%NG]).W2[k,:]/32 + b[k]
__device__ __align__(16) float g_G2[NG * DDIM];
// handoff counters (self-resetting each launch -> graph-replay safe)
__device__ int g_done = 0;
__device__ int g_fin  = 0;

typedef unsigned long long u64;
union F4U { float4 f; u64 u[2]; };

__device__ __forceinline__ u64 pack2(float x, float y) {
    u64 r; asm("mov.b64 %0, {%1,%2};" : "=l"(r) : "f"(x), "f"(y)); return r;
}
__device__ __forceinline__ void unpack2(u64 v, float& x, float& y) {
    asm("mov.b64 {%0,%1}, %2;" : "=f"(x), "=f"(y) : "l"(v));
}
__device__ __forceinline__ u64 fma2(u64 a, u64 b, u64 c) {
    u64 d; asm("fma.rn.f32x2 %0, %1, %2, %3;" : "=l"(d) : "l"(a), "l"(b), "l"(c)); return d;
}
// non-sinkable read-only load (immutable inputs only)
__device__ __forceinline__ float ldg_force(const float* p) {
    float v; asm volatile("ld.global.nc.f32 %0, [%1];" : "=f"(v) : "l"(p)); return v;
}
// L2-scope ops for producer<->consumer data (cross-block coherent, bypass L1)
__device__ __forceinline__ float4 ldg_cg128(const float* p) {
    float4 v;
    asm volatile("ld.global.cg.v4.f32 {%0,%1,%2,%3}, [%4];"
                 : "=f"(v.x), "=f"(v.y), "=f"(v.z), "=f"(v.w) : "l"(p));
    return v;
}
__device__ __forceinline__ void stg_cg(float* p, float v) {
    asm volatile("st.global.cg.f32 [%0], %1;" :: "l"(p), "f"(v) : "memory");
}
__device__ __forceinline__ void arrive_release(int* p) {
    asm volatile("red.release.gpu.global.add.s32 [%0], 1;" :: "l"(p) : "memory");
}
__device__ __forceinline__ int ld_acquire(const int* p) {
    int v; asm volatile("ld.acquire.gpu.global.s32 %0, [%1];" : "=r"(v) : "l"(p));
    return v;
}

// ---------------------------------------------------------------------------
// maxBlocksPerMP=6 caps regs at ~84: main phase (the hot path) fits; the
// producer phase spills a little to local, which is noise for 392 short blocks.
// ---------------------------------------------------------------------------
__global__ __launch_bounds__(128, 6) void fused_kernel(
    const float* __restrict__ embeds,
    const int* __restrict__ anchor,
    const float* __restrict__ Wh,
    const float* __restrict__ bias,
    const float* __restrict__ dists,
    float* __restrict__ out)
{
    __shared__ __align__(16) float smem[MROWS * 65 + MROWS * DDIM];  // 8256 fl
    float* Os = smem;                     // main: [64][65]
    float* Gs = smem + MROWS * 65;        // main: [64][64]
    float* Cs = smem + MROWS * 65;        // main: C stage (alias of Gs)
    float* Wt  = smem;                    // prep: 4160 fl
    float* Buf = smem + 4160;             // prep: 4096 fl available

    const int t = threadIdx.x;
    const int bid = blockIdx.x;
    const int lane = t & 31;
    const int wid = t >> 5;
    const int c0 = wid * 16;
    const int rowbase = bid * MROWS;

    // ===================== producer phase =====================
    if (bid < NPREPG) {
        const int u0 = bid * UB;
        // stage W2 transposed: Wt[d*65+k] = Wh[k*128+64+d]
        #pragma unroll
        for (int i = 0; i < 8; i++) {
            int idx = t + i * 128;            // 1024 float4 tasks
            int k = idx >> 4, dq = idx & 15;
            float4 v = *(const float4*)(Wh + k * 2 * DDIM + DDIM + 4 * dq);
            Wt[(4 * dq + 0) * 65 + k] = v.x;
            Wt[(4 * dq + 1) * 65 + k] = v.y;
            Wt[(4 * dq + 2) * 65 + k] = v.z;
            Wt[(4 * dq + 3) * 65 + k] = v.w;
        }
        // phase A: 288 tasks of 8-row float4 partial sums (u's u0..u0+8)
        float* Ps = Buf;                      // [18][64]
        for (int s = t; s < (UB + 1) * 32; s += 128) {
            int uu = s >> 5, h = (s >> 4) & 1, c = s & 15;
            int rb = 16 * (u0 + uu);
            if (rb >= NTOT) rb -= NTOT;       // wrap (u=NG neighbor)
            const float4* src = (const float4*)(embeds + (size_t)(rb + 8 * h) * DDIM) + c;
            float4 a = make_float4(0.f, 0.f, 0.f, 0.f);
            #pragma unroll
            for (int j = 0; j < 8; j++) {
                float4 v = src[j * 16];
                a.x += v.x; a.y += v.y; a.z += v.z; a.w += v.w;
            }
            float* dst = Ps + (uu * 2 + h) * DDIM + 4 * c;
            dst[0] = a.x; dst[1] = a.y; dst[2] = a.z; dst[3] = a.w;
        }
        __syncthreads();
        // phase B: E32[uu][d]  (512 tasks)
        float* E32 = Buf + 18 * DDIM;         // [8][64]
        #pragma unroll
        for (int i = 0; i < 4; i++) {
            int s = t + i * 128;
            int uu = s >> 6, d = s & 63;
            E32[uu * DDIM + d] =
                Ps[(2 * uu) * DDIM + d] + Ps[(2 * uu + 1) * DDIM + d] +
                Ps[(2 * uu + 2) * DDIM + d] + Ps[(2 * uu + 3) * DDIM + d];
        }
        __syncthreads();
        // phase C: 4 outputs/thread, written with .cg (straight to L2)
        {
            int k = t & 63;
            int uu0 = t >> 6;                 // 0 or 1
            float b = __ldg(bias + k);
            #pragma unroll
            for (int ii = 0; ii < 4; ii++) {
                int uu = uu0 + 2 * ii;
                int u = u0 + uu;
                float s = 0.f;
                #pragma unroll 16
                for (int d = 0; d < DDIM; d++)
                    s += E32[uu * DDIM + d] * Wt[d * 65 + k];
                if (u < NG)
                    stg_cg(g_G2 + u * DDIM + k, s * (1.0f / 32.0f) + b);
            }
        }
        // release: every thread fences its own writes, then one arrive
        __syncthreads();
        __threadfence();
        __syncthreads();
        if (t == 0) arrive_release(&g_done);
    } else if (bid == NPREPG) {
        // anchor projections -> g_C
        #pragma unroll
        for (int i = 0; i < 8; i++) {
            int idx = t + i * 128;            // W1 -> Wt[k*65+d]
            int k = idx >> 4, dq = idx & 15;
            float4 v = *(const float4*)(Wh + k * 2 * DDIM + 4 * dq);
            Wt[k * 65 + 4 * dq + 0] = v.x;
            Wt[k * 65 + 4 * dq + 1] = v.y;
            Wt[k * 65 + 4 * dq + 2] = v.z;
            Wt[k * 65 + 4 * dq + 3] = v.w;
        }
        float* Es = Buf;                      // [32][65] = 2080 fl
        #pragma unroll
        for (int i = 0; i < 4; i++) {
            int idx = t + i * 128;            // 512 float4 tasks
            int a = idx >> 4, c = idx & 15;
            float4 v = *(const float4*)(embeds + (size_t)anchor[a] * DDIM + 4 * c);
            Es[a * 65 + 4 * c + 0] = v.x;
            Es[a * 65 + 4 * c + 1] = v.y;
            Es[a * 65 + 4 * c + 2] = v.z;
            Es[a * 65 + 4 * c + 3] = v.w;
        }
        __syncthreads();
        {
            int ia = t >> 2;                  // 0..31
            int kb = (t & 3) * 16;
            #pragma unroll
            for (int half = 0; half < 2; half++) {     // 8 k's at a time (reg cap)
                float s[8];
                #pragma unroll
                for (int kk = 0; kk < 8; kk++) s[kk] = 0.f;
                #pragma unroll 8
                for (int d = 0; d < DDIM; d++) {
                    float e = Es[ia * 65 + d];
                    #pragma unroll
                    for (int kk = 0; kk < 8; kk++)
                        s[kk] += e * Wt[(kb + half * 8 + kk) * 65 + d];
                }
                #pragma unroll
                for (int kk = 0; kk < 8; kk++)
                    stg_cg(g_C + ia * DDIM + kb + half * 8 + kk, s[kk] * (1.0f / 32.0f));
            }
        }
        __syncthreads();
        __threadfence();
        __syncthreads();
        if (t == 0) arrive_release(&g_done);
    }

    // ===================== main phase (all blocks) =====================
    int n0 = rowbase + lane;      if (n0 >= NTOT) n0 = NTOT - 1;
    int n1 = rowbase + 32 + lane; if (n1 >= NTOT) n1 = NTOT - 1;

    // dists loads (immutable input) — overlap the spin below
    float dv0[32], dv1[32];
    #pragma unroll
    for (int a = 0; a < 32; a++) dv0[a] = ldg_force(dists + (size_t)a * NTOT + n0);
    #pragma unroll
    for (int a = 0; a < 32; a++) dv1[a] = ldg_force(dists + (size_t)a * NTOT + n1);

    // acquire spin (backoff keeps 782 pollers off the L2 line)
    if (t == 0) {
        while (ld_acquire(&g_done) < NPREP) { __nanosleep(64); }
        __threadfence();
    }
    __syncthreads();

    {   // stage C from L2 (cg: coherent with producers' .cg writes)
        #pragma unroll
        for (int i = 0; i < 4; i++) {
            int idx = t + i * 128;
            *(float4*)(Cs + 4 * idx) = ldg_cg128(g_C + 4 * idx);
        }
    }
    __syncthreads();

    u64 acc0[8], acc1[8];
    #pragma unroll
    for (int q = 0; q < 8; q++) { acc0[q] = 0ULL; acc1[q] = 0ULL; }

    const float4* Crow = (const float4*)Cs + (c0 >> 2);
    #pragma unroll
    for (int a = 0; a < 32; a++) {
        u64 b0 = pack2(dv0[a], dv0[a]);
        u64 b1 = pack2(dv1[a], dv1[a]);
        #pragma unroll
        for (int qq = 0; qq < 4; qq++) {
            F4U cu; cu.f = Crow[a * 16 + qq];              // broadcast LDS.128
            acc0[2 * qq]     = fma2(b0, cu.u[0], acc0[2 * qq]);
            acc0[2 * qq + 1] = fma2(b0, cu.u[1], acc0[2 * qq + 1]);
            acc1[2 * qq]     = fma2(b1, cu.u[0], acc1[2 * qq]);
            acc1[2 * qq + 1] = fma2(b1, cu.u[1], acc1[2 * qq + 1]);
        }
    }

    // coalesced G2 row loads (held in regs across the alias barrier)
    float4 gv[8];
    #pragma unroll
    for (int i = 0; i < 8; i++) {
        int idx = t + i * 128;
        int gr = idx >> 4, c = idx & 15;
        int u = (2 * (rowbase + gr)) % NG;
        gv[i] = ldg_cg128(g_G2 + (size_t)u * DDIM + 4 * c);
    }

    __syncthreads();   // Cs dead -> reuse as Gs

    #pragma unroll
    for (int i = 0; i < 8; i++) {
        int idx = t + i * 128;
        int gr = idx >> 4, c = idx & 15;
        *(float4*)(Gs + gr * DDIM + 4 * c) = gv[i];
    }
    #pragma unroll
    for (int qq = 0; qq < 8; qq++) {
        float x, y;
        unpack2(acc0[qq], x, y);
        Os[lane * 65 + c0 + 2 * qq]     = x;
        Os[lane * 65 + c0 + 2 * qq + 1] = y;
        unpack2(acc1[qq], x, y);
        Os[(32 + lane) * 65 + c0 + 2 * qq]     = x;
        Os[(32 + lane) * 65 + c0 + 2 * qq + 1] = y;
    }
    __syncthreads();

    // all-smem epilogue
    const int rows_valid = NTOT - rowbase;
    const int k = t & 63;
    int r = t >> 6;
    #pragma unroll 8
    for (int i = 0; i < MROWS / 2; i++, r += 2) {
        if (r < rows_valid)
            out[(size_t)(rowbase + r) * DDIM + k] = Os[r * 65 + k] + Gs[r * DDIM + k];
    }

    // self-reset counters (last block) -> graph-replay safe
    if (t == 0) {
        int f;
        asm volatile("atom.global.add.s32 %0, [%1], 1;" : "=r"(f) : "l"(&g_fin) : "memory");
        if (f == GRID - 1) {
            asm volatile("st.global.cg.s32 [%0], 0;" :: "l"(&g_done) : "memory");
            asm volatile("st.global.cg.s32 [%0], 0;" :: "l"(&g_fin) : "memory");
        }
    }
}

// ---------------------------------------------------------------------------
extern "C" void kernel_launch(void* const* d_in, const int* in_sizes, int n_in,
                              void* d_out, int out_size)
{
    const float* embeds = (const float*)d_in[0];   // (N, D)
    const float* dists  = (const float*)d_in[1];   // (A, N)
    const int*   anchor = (const int*)d_in[2];     // (A,)
    const float* Wh     = (const float*)d_in[3];   // (D, 2D)
    const float* bias   = (const float*)d_in[4];   // (D,)
    float* out = (float*)d_out;
    (void)in_sizes; (void)n_in; (void)out_size;

    fused_kernel<<<GRID, 128>>>(embeds, anchor, Wh, bias, dists, out);
}

// round 17
// speedup vs baseline: 1.1875x; 1.1875x over previous
#include <cuda_runtime.h>

#define NTOT 50000
#define AANCH 32
#define DDIM 64
#define NG 3125                      // NTOT/16
#define UB 4                         // u's per prep G-block
#define NBG ((NG + UB - 1) / UB)     // 782
#define MROWS 64                     // rows per main block

// plain C: g_C[a*64+k] = (1/32) * embeds[anchor[a]] . W1[k,:]
__device__ __align__(16) float g_C[AANCH * DDIM];
// pair-G: g_G2[u*64+k] = (E16[u]+E16[(u+1)%NG]).W2[k,:]/32 + b[k]
__device__ __align__(16) float g_G2[NG * DDIM];

typedef unsigned long long u64;
union F4U { float4 f; u64 u[2]; };

__device__ __forceinline__ u64 pack2(float x, float y) {
    u64 r; asm("mov.b64 %0, {%1,%2};" : "=l"(r) : "f"(x), "f"(y)); return r;
}
__device__ __forceinline__ void unpack2(u64 v, float& x, float& y) {
    asm("mov.b64 {%0,%1}, %2;" : "=f"(x), "=f"(y) : "l"(v));
}
__device__ __forceinline__ u64 fma2(u64 a, u64 b, u64 c) {
    u64 d; asm("fma.rn.f32x2 %0, %1, %2, %3;" : "=l"(d) : "l"(a), "l"(b), "l"(c)); return d;
}
// non-sinkable global loads
__device__ __forceinline__ float ldg_force(const float* p) {
    float v; asm volatile("ld.global.nc.f32 %0, [%1];" : "=f"(v) : "l"(p)); return v;
}
__device__ __forceinline__ float4 ldg_force128(const float* p) {
    float4 v;
    asm volatile("ld.global.nc.v4.f32 {%0,%1,%2,%3}, [%4];"
                 : "=f"(v.x), "=f"(v.y), "=f"(v.z), "=f"(v.w) : "l"(p));
    return v;
}

// ---------------------------------------------------------------------------
// prep: bid 0 -> anchor projections (g_C). bid 1..NBG: 4 G2 rows each
// (E16 computed in-block incl. the u0+4 neighbor, with wrap). 256 threads.
// 783 blocks -> 5.3 blocks/SM: DRAM latency of the embeds read well hidden.
// ---------------------------------------------------------------------------
__global__ __launch_bounds__(256) void prep_kernel(
    const float* __restrict__ embeds,
    const int* __restrict__ anchor,
    const float* __restrict__ Wh,
    const float* __restrict__ bias)
{
    __shared__ float Wt[DDIM * 65];   // G path: W2t[d*65+k]. anchor path: W1[k*65+d]
    __shared__ float Buf[2080];       // G: Ps[10][64] + E32[4][64] | anchors: Es[32][65]
    const int t = threadIdx.x;

    if (blockIdx.x == 0) {
        // ---- anchor projections -> g_C
        #pragma unroll
        for (int i = 0; i < 16; i++) {
            int idx = t + i * 256;
            int k = idx >> 6, d = idx & 63;
            Wt[k * 65 + d] = Wh[k * 2 * DDIM + d];             // W1[k][d]
        }
        float* Es = Buf;                                       // [32][65]
        #pragma unroll
        for (int i = 0; i < 8; i++) {
            int idx = t + i * 256;
            int a = idx >> 6, d = idx & 63;
            Es[a * 65 + d] = embeds[(size_t)anchor[a] * DDIM + d];
        }
        __syncthreads();
        int ia = t >> 3;
        int kbase = (t & 7) * 8;
        float s[8];
        #pragma unroll
        for (int kk = 0; kk < 8; kk++) s[kk] = 0.f;
        #pragma unroll 8
        for (int d = 0; d < DDIM; d++) {
            float e = Es[ia * 65 + d];
            #pragma unroll
            for (int kk = 0; kk < 8; kk++) s[kk] += e * Wt[(kbase + kk) * 65 + d];
        }
        #pragma unroll
        for (int kk = 0; kk < 8; kk++)
            g_C[ia * DDIM + kbase + kk] = s[kk] * (1.0f / 32.0f);
        return;
    }

    // ---- G path: 4 u's per block
    const int u0 = (blockIdx.x - 1) * UB;
    // stage W2 transposed: Wt[d*65+k] = Wh[k*128+64+d]  (1024 float4 tasks)
    #pragma unroll
    for (int i = 0; i < 4; i++) {
        int idx = t + i * 256;
        int k = idx >> 4, dq = idx & 15;
        float4 v = *(const float4*)(Wh + k * 2 * DDIM + DDIM + 4 * dq);
        Wt[(4 * dq + 0) * 65 + k] = v.x;
        Wt[(4 * dq + 1) * 65 + k] = v.y;
        Wt[(4 * dq + 2) * 65 + k] = v.z;
        Wt[(4 * dq + 3) * 65 + k] = v.w;
    }
    // phase A: 160 tasks of 8-row float4 partial sums (u's u0..u0+4)
    float* Ps = Buf;                      // [10][64]
    if (t < (UB + 1) * 32) {
        int uu = t >> 5, h = (t >> 4) & 1, c = t & 15;
        int rb = 16 * (u0 + uu);
        if (rb >= NTOT) rb -= NTOT;       // wrap (u = NG neighbor)
        const float4* src = (const float4*)(embeds + (size_t)(rb + 8 * h) * DDIM) + c;
        float4 a = make_float4(0.f, 0.f, 0.f, 0.f);
        #pragma unroll
        for (int j = 0; j < 8; j++) {
            float4 v = src[j * 16];
            a.x += v.x; a.y += v.y; a.z += v.z; a.w += v.w;
        }
        float* dst = Ps + (uu * 2 + h) * DDIM + 4 * c;
        dst[0] = a.x; dst[1] = a.y; dst[2] = a.z; dst[3] = a.w;
    }
    __syncthreads();
    // phase B: E32[uu][d] = Ps[2uu]+Ps[2uu+1]+Ps[2uu+2]+Ps[2uu+3]  (256 tasks)
    float* E32 = Buf + 10 * DDIM;         // [4][64]
    {
        int uu = t >> 6, d = t & 63;
        E32[uu * DDIM + d] =
            Ps[(2 * uu) * DDIM + d] + Ps[(2 * uu + 1) * DDIM + d] +
            Ps[(2 * uu + 2) * DDIM + d] + Ps[(2 * uu + 3) * DDIM + d];
    }
    __syncthreads();
    // phase C: exactly one output per thread
    {
        int k = t & 63, uu = t >> 6;
        int u = u0 + uu;
        float s = 0.f;
        #pragma unroll 16
        for (int d = 0; d < DDIM; d++)
            s += E32[uu * DDIM + d] * Wt[d * 65 + k];   // broadcast x stride-1
        if (u < NG)
            g_G2[u * DDIM + k] = s * (1.0f / 32.0f) + __ldg(bias + k);
    }
}

// ---------------------------------------------------------------------------
// main (R13 verbatim): block = 64 rows x 64 cols, 128 threads;
// warp = 64 rows x 16 cols. Coalesced Gs staging, all-smem epilogue, PDL.
// ---------------------------------------------------------------------------
__global__ __launch_bounds__(128) void main_kernel(
    const float* __restrict__ dists,
    float* __restrict__ out)
{
    __shared__ __align__(16) float smem[MROWS * 65 + MROWS * DDIM];   // 33 KB
    float* Os = smem;
    float* Gs = smem + MROWS * 65;
    float* Cs = smem + MROWS * 65;        // mainloop-phase alias of Gs region
    const int t = threadIdx.x;
    const int lane = t & 31;
    const int wid = t >> 5;
    const int c0 = wid * 16;
    const int rowbase = blockIdx.x * MROWS;

    int n0 = rowbase + lane;      if (n0 >= NTOT) n0 = NTOT - 1;
    int n1 = rowbase + 32 + lane; if (n1 >= NTOT) n1 = NTOT - 1;

    // dists loads (prep-independent): issue before the PDL wait
    float dv0[32], dv1[32];
    #pragma unroll
    for (int a = 0; a < 32; a++) dv0[a] = ldg_force(dists + (size_t)a * NTOT + n0);
    #pragma unroll
    for (int a = 0; a < 32; a++) dv1[a] = ldg_force(dists + (size_t)a * NTOT + n1);

    asm volatile("griddepcontrol.wait;" ::: "memory");

    {   // stage C into Cs (8 KB, L2-resident)
        float4* dst = (float4*)Cs;
        const float4* src = (const float4*)g_C;
        #pragma unroll
        for (int i = 0; i < 4; i++)
            dst[t + i * 128] = src[t + i * 128];
    }
    __syncthreads();

    u64 acc0[8], acc1[8];
    #pragma unroll
    for (int q = 0; q < 8; q++) { acc0[q] = 0ULL; acc1[q] = 0ULL; }

    const float4* Crow = (const float4*)Cs + (c0 >> 2);
    #pragma unroll
    for (int a = 0; a < 32; a++) {
        u64 b0 = pack2(dv0[a], dv0[a]);
        u64 b1 = pack2(dv1[a], dv1[a]);
        #pragma unroll
        for (int qq = 0; qq < 4; qq++) {
            F4U cu; cu.f = Crow[a * 16 + qq];              // broadcast LDS.128
            acc0[2 * qq]     = fma2(b0, cu.u[0], acc0[2 * qq]);
            acc0[2 * qq + 1] = fma2(b0, cu.u[1], acc0[2 * qq + 1]);
            acc1[2 * qq]     = fma2(b1, cu.u[0], acc1[2 * qq]);
            acc1[2 * qq + 1] = fma2(b1, cu.u[1], acc1[2 * qq + 1]);
        }
    }

    // coalesced G2 loads: task (gr, c), lanes 0-15 read one 256B row segment
    float4 gv[8];
    #pragma unroll
    for (int i = 0; i < 8; i++) {
        int idx = t + i * 128;
        int gr = idx >> 4, c = idx & 15;
        int u = (2 * (rowbase + gr)) % NG;
        gv[i] = ldg_force128(g_G2 + (size_t)u * DDIM + 4 * c);
    }

    __syncthreads();   // everyone done reading Cs; safe to overwrite with Gs

    #pragma unroll
    for (int i = 0; i < 8; i++) {
        int idx = t + i * 128;
        int gr = idx >> 4, c = idx & 15;
        *(float4*)(Gs + gr * DDIM + 4 * c) = gv[i];
    }
    #pragma unroll
    for (int qq = 0; qq < 8; qq++) {
        float x, y;
        unpack2(acc0[qq], x, y);
        Os[lane * 65 + c0 + 2 * qq]     = x;
        Os[lane * 65 + c0 + 2 * qq + 1] = y;
        unpack2(acc1[qq], x, y);
        Os[(32 + lane) * 65 + c0 + 2 * qq]     = x;
        Os[(32 + lane) * 65 + c0 + 2 * qq + 1] = y;
    }
    __syncthreads();

    // all-smem epilogue: no global loads, no wrap ALU
    const int rows_valid = NTOT - rowbase;
    const int k = t & 63;
    int r = t >> 6;
    #pragma unroll 8
    for (int i = 0; i < MROWS / 2; i++, r += 2) {
        if (r < rows_valid)
            out[(size_t)(rowbase + r) * DDIM + k] = Os[r * 65 + k] + Gs[r * DDIM + k];
    }
}

// ---------------------------------------------------------------------------
extern "C" void kernel_launch(void* const* d_in, const int* in_sizes, int n_in,
                              void* d_out, int out_size)
{
    const float* embeds = (const float*)d_in[0];   // (N, D)
    const float* dists  = (const float*)d_in[1];   // (A, N)
    const int*   anchor = (const int*)d_in[2];     // (A,)
    const float* Wh     = (const float*)d_in[3];   // (D, 2D)
    const float* bias   = (const float*)d_in[4];   // (D,)
    float* out = (float*)d_out;
    (void)in_sizes; (void)n_in; (void)out_size;

    prep_kernel<<<NBG + 1, 256>>>(embeds, anchor, Wh, bias);

    // PDL: main launches early; its dists loads overlap prep's tail.
    cudaLaunchConfig_t cfg = {};
    cfg.gridDim  = dim3((NTOT + MROWS - 1) / MROWS);   // 782
    cfg.blockDim = dim3(128);
    cudaLaunchAttribute attr[1];
    attr[0].id = cudaLaunchAttributeProgrammaticStreamSerialization;
    attr[0].val.programmaticStreamSerializationAllowed = 1;
    cfg.attrs = attr;
    cfg.numAttrs = 1;
    cudaLaunchKernelEx(&cfg, main_kernel, dists, out);
}